// round 1
// baseline (speedup 1.0000x reference)
#include <cuda_runtime.h>

#define CIN 256
#define COUT 256
#define NB 32

#define WSZ (CIN * 9 * COUT)          // 589824 per path
#define ZSZ (NB * COUT * 6 * 6)       // 294912 per branch
#define XSZ (NB * COUT * 30 * 30)     // 7372800 per branch
#define OSZ (NB * COUT * 25 * 25)     // 5120000 per branch

// Scratch (static device memory — no allocation).
// paths: 0=cls_z, 1=cls_x, 2=reg_z, 3=reg_x ; branches: 0=cls, 1=reg
__device__ float g_wt[4][WSZ];        // [path][cin][tap][oc]  (BN-folded, oc-contiguous)
__device__ float g_bias[4][COUT];
__device__ float g_zf[2][ZSZ];
__device__ float g_xf[2][XSZ];

// ---------------------------------------------------------------------------
// Prep: fold BN into weights + transpose OIHW -> [cin][tap][oc]
// ---------------------------------------------------------------------------
__global__ void prep_kernel(const float* __restrict__ w,
                            const float* __restrict__ g,
                            const float* __restrict__ b,
                            const float* __restrict__ m,
                            const float* __restrict__ v,
                            int path) {
    int idx = blockIdx.x * blockDim.x + threadIdx.x;
    if (idx < COUT) {
        float inv = g[idx] * rsqrtf(v[idx] + 1e-5f);
        g_bias[path][idx] = b[idx] - m[idx] * inv;
    }
    for (int i = idx; i < WSZ; i += gridDim.x * blockDim.x) {
        int oc   = i % COUT;
        int rest = i / COUT;     // cin*9 + tap
        int tap  = rest % 9;
        int cin  = rest / 9;
        float inv = g[oc] * rsqrtf(v[oc] + 1e-5f);
        g_wt[path][i] = w[oc * (CIN * 9) + cin * 9 + tap] * inv;
    }
}

// ---------------------------------------------------------------------------
// Conv 3x3 VALID + folded BN bias.
// Block: 64 oc x (8x8) output pixels, 256 threads.
// Thread: 4 oc x 4 pixels (one row of 4 contiguous output cols).
// ---------------------------------------------------------------------------
template <int IH, int IW, int OH, int OW>
__global__ __launch_bounds__(256)
void conv_bn_kernel(const float* __restrict__ in,   // [NB][CIN][IH][IW]
                    const float* __restrict__ wt,   // [CIN][9][COUT]
                    const float* __restrict__ bias, // [COUT]
                    float* __restrict__ out) {      // [NB][COUT][OH][OW]
    constexpr int TOH = 8, TOW = 8;
    constexpr int TILES_X = (OW + TOW - 1) / TOW;
    constexpr int CK = 8;
    constexpr int ISTRIDE = 13;                     // conflict-avoiding row stride

    __shared__ float s_in[CK][TOH + 2][ISTRIDE];
    __shared__ float s_w[CK * 9 * 64];              // [ck][tap][64 oc]

    const int b    = blockIdx.x;
    const int ocb  = blockIdx.y * 64;
    const int tile = blockIdx.z;
    const int ty0  = (tile / TILES_X) * TOH;
    const int tx0  = (tile % TILES_X) * TOW;

    const int tid  = threadIdx.x;
    const int ocg  = tid >> 4;                      // 0..15 (4 oc each)
    const int pix  = tid & 15;                      // 0..15
    const int prow = pix >> 1;                      // 0..7
    const int pcol = (pix & 1) * 4;                 // 0 or 4

    float acc[4][4];
#pragma unroll
    for (int o = 0; o < 4; o++)
#pragma unroll
        for (int p = 0; p < 4; p++) acc[o][p] = 0.f;

    const float* inb = in + (long)b * CIN * IH * IW;

    for (int c0 = 0; c0 < CIN; c0 += CK) {
        __syncthreads();
        // stage input patch CK x 10 x 10 (zero-pad OOB)
        for (int i = tid; i < CK * (TOH + 2) * (TOW + 2); i += 256) {
            int cc = i / ((TOH + 2) * (TOW + 2));
            int r  = (i / (TOW + 2)) % (TOH + 2);
            int cl = i % (TOW + 2);
            int gy = ty0 + r, gx = tx0 + cl;
            float val = 0.f;
            if (gy < IH && gx < IW)
                val = inb[(long)(c0 + cc) * IH * IW + gy * IW + gx];
            s_in[cc][r][cl] = val;
        }
        // stage weights CK x 9 x 64 (coalesced float4)
        const float* wsrc = wt + (long)c0 * 9 * COUT + ocb;
        for (int i = tid; i < CK * 9 * 16; i += 256) {
            int seg = i >> 4;                       // ck*9 + tap
            int o4  = (i & 15) * 4;
            ((float4*)s_w)[i] = *(const float4*)(wsrc + (long)seg * COUT + o4);
        }
        __syncthreads();

        for (int ck = 0; ck < CK; ck++) {
#pragma unroll
            for (int dy = 0; dy < 3; dy++) {
                float rr[6];
#pragma unroll
                for (int k = 0; k < 6; k++) rr[k] = s_in[ck][prow + dy][pcol + k];
#pragma unroll
                for (int dx = 0; dx < 3; dx++) {
                    float4 w4 = *(const float4*)&s_w[(ck * 9 + dy * 3 + dx) * 64 + ocg * 4];
#pragma unroll
                    for (int p = 0; p < 4; p++) {
                        acc[0][p] = fmaf(w4.x, rr[dx + p], acc[0][p]);
                        acc[1][p] = fmaf(w4.y, rr[dx + p], acc[1][p]);
                        acc[2][p] = fmaf(w4.z, rr[dx + p], acc[2][p]);
                        acc[3][p] = fmaf(w4.w, rr[dx + p], acc[3][p]);
                    }
                }
            }
        }
    }

    // epilogue
#pragma unroll
    for (int o = 0; o < 4; o++) {
        int oc = ocb + ocg * 4 + o;
        float bs = bias[oc];
        int oy = ty0 + prow;
        if (oy < OH) {
#pragma unroll
            for (int p = 0; p < 4; p++) {
                int ox = tx0 + pcol + p;
                if (ox < OW)
                    out[((long)b * COUT + oc) * (OH * OW) + oy * OW + ox] = acc[o][p] + bs;
            }
        }
    }
}

// ---------------------------------------------------------------------------
// Depthwise xcorr: out[b,c,i,j] = sum_{u,v} zf[b,c,u,v] * xf[b,c,i+u,j+v]
// One block per (b,c). 640 threads, 625 active outputs.
// ---------------------------------------------------------------------------
__global__ __launch_bounds__(640)
void xcorr_kernel(const float* __restrict__ zf,   // [B*C][36]
                  const float* __restrict__ xf,   // [B*C][900]
                  float* __restrict__ out) {      // [B*C][625]
    __shared__ float s_x[900];
    __shared__ float s_z[36];
    const int bc = blockIdx.x;
    const float* xp = xf + (long)bc * 900;
    const float* zp = zf + (long)bc * 36;
    const int tid = threadIdx.x;
    if (tid < 36) s_z[tid] = zp[tid];
    for (int i = tid; i < 900; i += 640) s_x[i] = xp[i];
    __syncthreads();
    if (tid < 625) {
        int oy = tid / 25, ox = tid % 25;
        float s = 0.f;
#pragma unroll
        for (int u = 0; u < 6; u++)
#pragma unroll
            for (int v = 0; v < 6; v++)
                s = fmaf(s_z[u * 6 + v], s_x[(oy + u) * 30 + ox + v], s);
        out[(long)bc * 625 + tid] = s;
    }
}

// ---------------------------------------------------------------------------
// Launch
// ---------------------------------------------------------------------------
extern "C" void kernel_launch(void* const* d_in, const int* in_sizes, int n_in,
                              void* d_out, int out_size) {
    const float* z = (const float*)d_in[0];
    const float* x = (const float*)d_in[1];

    // d_in order: z, x, then per path (w,g,b,m,v): cls_z, cls_x, reg_z, reg_x
    const float* P[4][5];
    for (int p = 0; p < 4; p++)
        for (int k = 0; k < 5; k++)
            P[p][k] = (const float*)d_in[2 + p * 5 + k];

    float *wt, *bias, *zf, *xf;
    cudaGetSymbolAddress((void**)&wt,   g_wt);
    cudaGetSymbolAddress((void**)&bias, g_bias);
    cudaGetSymbolAddress((void**)&zf,   g_zf);
    cudaGetSymbolAddress((void**)&xf,   g_xf);

    for (int p = 0; p < 4; p++)
        prep_kernel<<<256, 256>>>(P[p][0], P[p][1], P[p][2], P[p][3], P[p][4], p);

    // cls branch
    conv_bn_kernel<8, 8, 6, 6><<<dim3(32, 4, 1), 256>>>(z, wt + 0 * WSZ, bias + 0 * COUT, zf + 0 * ZSZ);
    conv_bn_kernel<32, 32, 30, 30><<<dim3(32, 4, 16), 256>>>(x, wt + 1 * WSZ, bias + 1 * COUT, xf + 0 * XSZ);
    // reg branch
    conv_bn_kernel<8, 8, 6, 6><<<dim3(32, 4, 1), 256>>>(z, wt + 2 * WSZ, bias + 2 * COUT, zf + 1 * ZSZ);
    conv_bn_kernel<32, 32, 30, 30><<<dim3(32, 4, 16), 256>>>(x, wt + 3 * WSZ, bias + 3 * COUT, xf + 1 * XSZ);

    float* out = (float*)d_out;
    xcorr_kernel<<<NB * COUT, 640>>>(zf + 0 * ZSZ, xf + 0 * XSZ, out);
    xcorr_kernel<<<NB * COUT, 640>>>(zf + 1 * ZSZ, xf + 1 * XSZ, out + OSZ);
}

// round 2
// speedup vs baseline: 1.5372x; 1.5372x over previous
#include <cuda_runtime.h>

#define CIN 256
#define COUT 256
#define NB 32

#define WSZ (CIN * 9 * COUT)          // 589824 per path
#define ZSZ (NB * COUT * 6 * 6)       // per branch
#define XSZ (NB * COUT * 30 * 30)     // per branch
#define OSZ (NB * COUT * 25 * 25)     // per branch

__device__ float g_wt[4][WSZ];        // [path][cin][tap][oc]  BN-folded
__device__ float g_bias[4][COUT];
__device__ float g_zf[2][ZSZ];
__device__ float g_xf[2][XSZ];

struct PrepArgs {
    const float* w[4];
    const float* g[4];
    const float* b[4];
    const float* m[4];
    const float* v[4];
};

// ---------------------------------------------------------------------------
// Packed fp32x2 FMA (Blackwell): d = a*b + d, two lanes per instruction.
// ---------------------------------------------------------------------------
__device__ __forceinline__ void fma2(unsigned long long& d,
                                     unsigned long long a,
                                     unsigned long long b) {
    asm("fma.rn.f32x2 %0, %1, %2, %0;" : "+l"(d) : "l"(a), "l"(b));
}

__device__ __forceinline__ float2 unpack2(unsigned long long v) {
    float2 r;
    asm("mov.b64 {%0, %1}, %2;" : "=f"(r.x), "=f"(r.y) : "l"(v));
    return r;
}

// ---------------------------------------------------------------------------
// Prep: fold BN into weights + transpose OIHW -> [cin][tap][oc], all 4 paths.
// ---------------------------------------------------------------------------
__global__ void prep_kernel(PrepArgs a) {
    const int path = blockIdx.y;
    const float* __restrict__ w = a.w[path];
    const float* __restrict__ g = a.g[path];
    const float* __restrict__ b = a.b[path];
    const float* __restrict__ m = a.m[path];
    const float* __restrict__ v = a.v[path];

    int idx = blockIdx.x * blockDim.x + threadIdx.x;
    int stride = gridDim.x * blockDim.x;
    if (idx < COUT) {
        float inv = g[idx] * rsqrtf(v[idx] + 1e-5f);
        g_bias[path][idx] = b[idx] - m[idx] * inv;
    }
    for (int i = idx; i < WSZ; i += stride) {
        int oc   = i % COUT;
        int rest = i / COUT;     // cin*9 + tap
        int tap  = rest % 9;
        int cin  = rest / 9;
        float inv = g[oc] * rsqrtf(v[oc] + 1e-5f);
        g_wt[path][i] = w[oc * (CIN * 9) + cin * 9 + tap] * inv;
    }
}

// ---------------------------------------------------------------------------
// Conv 3x3 VALID + folded BN bias, FFMA2 inner loop.
// Block: 64 oc x (8x8) output tile, 128 threads.
// Thread: 4 oc x 8 pixels (one full tile row) = 16 f32x2 accumulators.
// Input staged twice (original + shifted by 1) so every pixel pair is an
// aligned LDS.64; weights staged duplicated (w,w) so LDS.128 yields pairs.
// ---------------------------------------------------------------------------
template <int IH, int IW, int OH, int OW>
__global__ __launch_bounds__(128)
void conv_bn2_kernel(const float* __restrict__ in,   // [NB][CIN][IH][IW]
                     const float* __restrict__ wt,   // [CIN][9][COUT]
                     const float* __restrict__ bias, // [COUT]
                     float* __restrict__ out) {      // [NB][COUT][OH][OW]
    constexpr int TOH = 8, TOW = 8;
    constexpr int TILES_X = (OW + TOW - 1) / TOW;
    constexpr int CK = 8;
    constexpr int SA = 12;   // padded row stride (even, conflict-free)
    constexpr int SB = 10;   // shifted copy row stride (even, conflict-free)

    __shared__ __align__(16) float s_A[CK][TOH + 2][SA];  // in[c]
    __shared__ __align__(16) float s_B[CK][TOH + 2][SB];  // in[c+1]
    __shared__ __align__(16) float s_w[CK * 9 * 128];     // (w,w) dup, 64 oc

    const int b    = blockIdx.x;
    const int ocb  = blockIdx.y * 64;
    const int ty0  = (blockIdx.z / TILES_X) * TOH;
    const int tx0  = (blockIdx.z % TILES_X) * TOW;

    const int tid  = threadIdx.x;
    const int ocg  = tid >> 3;      // 0..15, 4 oc each
    const int prow = tid & 7;       // output row within tile

    unsigned long long acc[4][4];
#pragma unroll
    for (int o = 0; o < 4; o++)
#pragma unroll
        for (int p = 0; p < 4; p++) acc[o][p] = 0ull;

    const float* inb = in + (long)b * CIN * IH * IW;

#pragma unroll 1
    for (int c0 = 0; c0 < CIN; c0 += CK) {
        __syncthreads();
        // stage input patch CK x 10 x 10, plus shifted copy
        for (int i = tid; i < CK * 100; i += 128) {
            int cc  = i / 100;
            int rem = i - cc * 100;
            int r   = rem / 10;
            int cl  = rem - r * 10;
            int gy = ty0 + r, gx = tx0 + cl;
            float val = 0.f;
            if (gy < IH && gx < IW)
                val = inb[(long)(c0 + cc) * IH * IW + gy * IW + gx];
            s_A[cc][r][cl] = val;
            if (cl >= 1) s_B[cc][r][cl - 1] = val;
        }
        // stage weights CK x 9 x 64 oc, duplicated (w,w)
        const float* wsrc = wt + (long)c0 * 9 * COUT + ocb;
        for (int i = tid; i < CK * 9 * 16; i += 128) {
            int seg = i >> 4;                 // ck*9 + tap
            int o4  = (i & 15) * 4;
            float4 w4 = *(const float4*)(wsrc + (long)seg * COUT + o4);
            float4* dst = (float4*)&s_w[seg * 128 + o4 * 2];
            dst[0] = make_float4(w4.x, w4.x, w4.y, w4.y);
            dst[1] = make_float4(w4.z, w4.z, w4.w, w4.w);
        }
        __syncthreads();

#pragma unroll 2
        for (int ck = 0; ck < CK; ck++) {
#pragma unroll
            for (int dy = 0; dy < 3; dy++) {
                const float* rA = &s_A[ck][prow + dy][0];
                const float* rB = &s_B[ck][prow + dy][0];
                // even pairs (0,1)(2,3)(4,5)(6,7)(8,9); odd pairs via shifted copy
                unsigned long long e[5], od[4];
#pragma unroll
                for (int k = 0; k < 5; k++)
                    e[k] = *(const unsigned long long*)(rA + 2 * k);
#pragma unroll
                for (int k = 0; k < 4; k++)
                    od[k] = *(const unsigned long long*)(rB + 2 * k);

#pragma unroll
                for (int dx = 0; dx < 3; dx++) {
                    const float* wp = &s_w[(ck * 9 + dy * 3 + dx) * 128 + ocg * 8];
                    ulonglong2 wa = *(const ulonglong2*)(wp);      // (w0,w0),(w1,w1)
                    ulonglong2 wb = *(const ulonglong2*)(wp + 4);  // (w2,w2),(w3,w3)
#pragma unroll
                    for (int pp = 0; pp < 4; pp++) {
                        unsigned long long pv =
                            (dx == 0) ? e[pp] : (dx == 1) ? od[pp] : e[pp + 1];
                        fma2(acc[0][pp], wa.x, pv);
                        fma2(acc[1][pp], wa.y, pv);
                        fma2(acc[2][pp], wb.x, pv);
                        fma2(acc[3][pp], wb.y, pv);
                    }
                }
            }
        }
    }

    // epilogue
    const int oy = ty0 + prow;
    if (oy < OH) {
#pragma unroll
        for (int o = 0; o < 4; o++) {
            int oc = ocb + ocg * 4 + o;
            float bs = bias[oc];
            float* op = out + ((long)b * COUT + oc) * (OH * OW) + oy * OW + tx0;
#pragma unroll
            for (int pp = 0; pp < 4; pp++) {
                int ox = tx0 + pp * 2;
                float2 fv = unpack2(acc[o][pp]);
                fv.x += bs;
                fv.y += bs;
                if (ox + 1 < OW)      *(float2*)(op + pp * 2) = fv;
                else if (ox < OW)     op[pp * 2] = fv.x;
            }
        }
    }
}

// ---------------------------------------------------------------------------
// Depthwise xcorr: out[bc,i,j] = sum_{u,v} zf[bc,u,v] * xf[bc,i+u,j+v]
// ---------------------------------------------------------------------------
__global__ __launch_bounds__(640)
void xcorr_kernel(const float* __restrict__ zf,   // [B*C][36]
                  const float* __restrict__ xf,   // [B*C][900]
                  float* __restrict__ out) {      // [B*C][625]
    __shared__ float s_x[900];
    __shared__ float s_z[36];
    const int bc = blockIdx.x;
    const float* xp = xf + (long)bc * 900;
    const float* zp = zf + (long)bc * 36;
    const int tid = threadIdx.x;
    if (tid < 36) s_z[tid] = zp[tid];
    for (int i = tid; i < 900; i += 640) s_x[i] = xp[i];
    __syncthreads();
    if (tid < 625) {
        int oy = tid / 25, ox = tid % 25;
        float s = 0.f;
#pragma unroll
        for (int u = 0; u < 6; u++)
#pragma unroll
            for (int v = 0; v < 6; v++)
                s = fmaf(s_z[u * 6 + v], s_x[(oy + u) * 30 + ox + v], s);
        out[(long)bc * 625 + tid] = s;
    }
}

// ---------------------------------------------------------------------------
// Launch
// ---------------------------------------------------------------------------
extern "C" void kernel_launch(void* const* d_in, const int* in_sizes, int n_in,
                              void* d_out, int out_size) {
    const float* z = (const float*)d_in[0];
    const float* x = (const float*)d_in[1];

    PrepArgs pa;
    for (int p = 0; p < 4; p++) {
        pa.w[p] = (const float*)d_in[2 + p * 5 + 0];
        pa.g[p] = (const float*)d_in[2 + p * 5 + 1];
        pa.b[p] = (const float*)d_in[2 + p * 5 + 2];
        pa.m[p] = (const float*)d_in[2 + p * 5 + 3];
        pa.v[p] = (const float*)d_in[2 + p * 5 + 4];
    }

    float *wt, *bias, *zf, *xf;
    cudaGetSymbolAddress((void**)&wt,   g_wt);
    cudaGetSymbolAddress((void**)&bias, g_bias);
    cudaGetSymbolAddress((void**)&zf,   g_zf);
    cudaGetSymbolAddress((void**)&xf,   g_xf);

    prep_kernel<<<dim3(160, 4), 256>>>(pa);

    // cls branch (paths 0=cls_z, 1=cls_x)
    conv_bn2_kernel<8, 8, 6, 6><<<dim3(32, 4, 1), 128>>>(
        z, wt + 0 * WSZ, bias + 0 * COUT, zf + 0 * ZSZ);
    conv_bn2_kernel<32, 32, 30, 30><<<dim3(32, 4, 16), 128>>>(
        x, wt + 1 * WSZ, bias + 1 * COUT, xf + 0 * XSZ);
    // reg branch (paths 2=reg_z, 3=reg_x)
    conv_bn2_kernel<8, 8, 6, 6><<<dim3(32, 4, 1), 128>>>(
        z, wt + 2 * WSZ, bias + 2 * COUT, zf + 1 * ZSZ);
    conv_bn2_kernel<32, 32, 30, 30><<<dim3(32, 4, 16), 128>>>(
        x, wt + 3 * WSZ, bias + 3 * COUT, xf + 1 * XSZ);

    float* out = (float*)d_out;
    xcorr_kernel<<<NB * COUT, 640>>>(zf + 0 * ZSZ, xf + 0 * XSZ, out);
    xcorr_kernel<<<NB * COUT, 640>>>(zf + 1 * ZSZ, xf + 1 * XSZ, out + OSZ);
}

// round 4
// speedup vs baseline: 3.2810x; 2.1344x over previous
#include <cuda_runtime.h>
#include <cuda_bf16.h>
#include <cstdint>

#define CIN 256
#define COUT 256
#define NB 32
#define ZSZ (NB * COUT * 36)
#define XSZ (NB * COUT * 900)
#define OSZ (NB * COUT * 625)
#define WB_PER_PATH (9 * 256 * 512)

__device__ __nv_bfloat16 g_wb[4][WB_PER_PATH];  // [path][tap][oc][hi 256 | lo 256]
__device__ float g_bias[4][COUT];
__device__ float g_zf[2][ZSZ];
__device__ float g_xf[2][XSZ];

struct PrepArgs {
    const float* w[4];
    const float* g[4];
    const float* b[4];
    const float* m[4];
    const float* v[4];
};

// ============================ helpers ========================================
__device__ __forceinline__ uint32_t smem_u32(const void* p) {
    uint32_t a;
    asm("{ .reg .u64 t; cvta.to.shared.u64 t, %1; cvt.u32.u64 %0, t; }"
        : "=r"(a) : "l"(p));
    return a;
}

__device__ __forceinline__ void cp16(uint32_t dst, const void* src) {
    asm volatile("cp.async.cg.shared.global [%0], [%1], 16;"
                 :: "r"(dst), "l"(src));
}
__device__ __forceinline__ void cp_commit() {
    asm volatile("cp.async.commit_group;" ::: "memory");
}
template <int N>
__device__ __forceinline__ void cp_wait() {
    asm volatile("cp.async.wait_group %0;" :: "n"(N) : "memory");
}

#define LDSM4(r, addr)                                                         \
    asm volatile("ldmatrix.sync.aligned.m8n8.x4.shared.b16 {%0,%1,%2,%3},[%4];"\
        : "=r"((r)[0]), "=r"((r)[1]), "=r"((r)[2]), "=r"((r)[3]) : "r"(addr))

#define MMA(d, a, b0, b1)                                                      \
    asm volatile("mma.sync.aligned.m16n8k16.row.col.f32.bf16.bf16.f32 "        \
        "{%0,%1,%2,%3}, {%4,%5,%6,%7}, {%8,%9}, {%0,%1,%2,%3};"                \
        : "+f"((d)[0]), "+f"((d)[1]), "+f"((d)[2]), "+f"((d)[3])               \
        : "r"((a)[0]), "r"((a)[1]), "r"((a)[2]), "r"((a)[3]),                  \
          "r"(b0), "r"(b1))

// ============================ prep ===========================================
__global__ void prep_kernel(PrepArgs a) {
    const int TOTAL = 4 * 9 * 256 * 256;
    for (int i = blockIdx.x * blockDim.x + threadIdx.x; i < TOTAL;
         i += gridDim.x * blockDim.x) {
        int path = i / (9 * 256 * 256);
        int q    = i % (9 * 256 * 256);
        int tap  = q >> 16;
        int oc   = (q >> 8) & 255;
        int cin  = q & 255;
        float inv = a.g[path][oc] * rsqrtf(a.v[path][oc] + 1e-5f);
        float ws  = a.w[path][oc * 2304 + cin * 9 + tap] * inv;
        __nv_bfloat16 hi = __float2bfloat16(ws);
        __nv_bfloat16 lo = __float2bfloat16(ws - __bfloat162float(hi));
        g_wb[path][(tap * 256 + oc) * 512 + cin]       = hi;
        g_wb[path][(tap * 256 + oc) * 512 + 256 + cin] = lo;
        if (i < 4 * 256) {
            int p2 = i >> 8, oc2 = i & 255;
            float inv2 = a.g[p2][oc2] * rsqrtf(a.v[p2][oc2] + 1e-5f);
            g_bias[p2][oc2] = a.b[p2][oc2] - a.m[p2][oc2] * inv2;
        }
    }
}

// ============================ conv (HMMA implicit GEMM) ======================
// Block: M=256 pixels x N=128 oc, K=2304 (256 cin x 9 taps), bf16 3-term split.
// 8 warps = 4(M) x 2(N); warp tile 64x64 via m16n8k16 mma.sync.
// blocks 0..511 : x-mode (img 32, rowtile 4, oct 2, branch 2)
// blocks 512..543: z-mode (imgquad 8, oct 2, branch 2)
#define BSTRIDE_B 272u               // B row stride bytes (136 bf16)
#define BBUFB     34816u             // one B buffer bytes (128*272)
#define RAW_OFF   69632u             // raw region byte offset (2 B bufs)
#define RAW_SLOTS 352
#define SLAB      (RAW_SLOTS * 72)   // elems per component
#define SLABB     (SLAB * 2)         // bytes
#define CONV_SMEM (RAW_OFF + 2u * SLABB)   // 171008

__device__ __forceinline__ void copy_B(uint32_t sBu, const __nv_bfloat16* wb,
                                       int ocb, int g, int tid) {
    const int ch = g / 9, tap = g - ch * 9, buf = g & 1;
    const int c0 = ch * 64;
    const __nv_bfloat16* base = wb + (size_t)(tap * 256 + ocb) * 512;
    for (int id = tid; id < 2048; id += 256) {
        int n = id >> 4, q = id & 15, comp = q >> 3, kq = q & 7;
        uint32_t dst = sBu + buf * BBUFB + n * BSTRIDE_B + comp * 128 + kq * 16;
        cp16(dst, base + (size_t)n * 512 + comp * 256 + c0 + kq * 8);
    }
    cp_commit();
}

__global__ __launch_bounds__(256, 1)
void conv_mma_kernel(const float* __restrict__ zin,
                     const float* __restrict__ xin) {
    extern __shared__ __align__(16) char smem[];
    __nv_bfloat16* sRaw = (__nv_bfloat16*)(smem + RAW_OFF);
    float* sEp = (float*)smem;

    const int tid = threadIdx.x, lid = tid & 31, wid = tid >> 5;
    const int warp_m = wid >> 1, warp_n = wid & 1;
    const uint32_t sBu  = smem_u32(smem);
    const uint32_t rawu = sBu + RAW_OFF;

    const int bid = blockIdx.x;
    const bool zmode = (bid >= 512);
    int img0, row0, ocb, branch;
    if (zmode) {
        int zb = bid - 512;             // 0..31
        img0 = (zb & 7) * 4;
        row0 = 0;
        ocb = ((zb >> 3) & 1) * 128;
        branch = zb >> 4;
    } else {
        img0 = bid & 31;
        row0 = ((bid >> 5) & 3) * 8;
        ocb = ((bid >> 7) & 1) * 128;
        branch = bid >> 8;
    }
    const int path = zmode ? 2 * branch : 1 + 2 * branch;
    const __nv_bfloat16* wb = g_wb[path];
    const float* in = zmode ? zin : xin;
    float* outp = zmode ? g_zf[branch] : g_xf[branch];

    float acc[4][8][4];
#pragma unroll
    for (int t = 0; t < 4; t++)
#pragma unroll
        for (int j = 0; j < 8; j++)
#pragma unroll
            for (int e = 0; e < 4; e++) acc[t][j][e] = 0.f;

    copy_B(sBu, wb, ocb, 0, tid);

    const int rawcnt = (zmode ? 256 : 352) * 64;

#pragma unroll 1
    for (int g = 0; g < 36; g++) {
        const int ch = g / 9, tap = g - ch * 9, buf = g & 1;
        if (tap == 0) {
            // stage raw input for this cin-chunk (prev mma done: loop-end sync)
            const int c0 = ch * 64;
            for (int id = tid; id < rawcnt; id += 256) {
                int c, m;
                float v;
                if (zmode) {
                    c = id >> 8; m = id & 255;
                    int slot = m >> 6, p2 = m & 63;
                    v = in[(((size_t)(img0 + slot) * CIN + c0 + c) << 6) + p2];
                } else {
                    c = id / 352; m = id - c * 352;
                    int gy = row0 + (m >> 5), gx = m & 31;
                    v = (gy < 32)
                        ? in[(((size_t)img0 * CIN + c0 + c) * 32 + gy) * 32 + gx]
                        : 0.f;
                }
                __nv_bfloat16 hi = __float2bfloat16(v);
                __nv_bfloat16 lo = __float2bfloat16(v - __bfloat162float(hi));
                sRaw[m * 72 + c]        = hi;
                sRaw[SLAB + m * 72 + c] = lo;
            }
        }
        if (g + 1 < 36) { copy_B(sBu, wb, ocb, g + 1, tid); cp_wait<1>(); }
        else            { cp_wait<0>(); }
        __syncthreads();

        // per-tap ldmatrix lane addresses
        const int dy = tap / 3, dx = tap - dy * 3;
        uint32_t aaddr[4], baddr[4];
#pragma unroll
        for (int t = 0; t < 4; t++) {
            int m = warp_m * 64 + t * 16 + (lid & 7) + ((lid >> 3) & 1) * 8;
            int pix;
            if (zmode) {
                int slot = m >> 6, p = m & 63;
                pix = (slot << 6) +
                      ((p < 36) ? ((p / 6 + dy) * 8 + (p % 6) + dx) : 0);
            } else {
                pix = m + dy * 32 + dx;
            }
            aaddr[t] = rawu + pix * 144 + ((lid >> 4) << 4);
        }
#pragma unroll
        for (int j = 0; j < 4; j++) {
            int n = warp_n * 64 + j * 16 + (lid & 7) + (lid >> 4) * 8;
            baddr[j] = sBu + buf * BBUFB + n * BSTRIDE_B + (((lid >> 3) & 1) << 4);
        }

#pragma unroll 1
        for (int ks = 0; ks < 4; ks++) {
            uint32_t ah[4][4], al[4][4], bq[4][4];
#pragma unroll
            for (int t = 0; t < 4; t++) LDSM4(ah[t], aaddr[t] + ks * 32);
#pragma unroll
            for (int t = 0; t < 4; t++) LDSM4(al[t], aaddr[t] + ks * 32 + SLABB);
#pragma unroll
            for (int j = 0; j < 4; j++) LDSM4(bq[j], baddr[j] + ks * 32);
            // hi*hi
#pragma unroll
            for (int t = 0; t < 4; t++)
#pragma unroll
                for (int j = 0; j < 4; j++) {
                    MMA(acc[t][2 * j],     ah[t], bq[j][0], bq[j][1]);
                    MMA(acc[t][2 * j + 1], ah[t], bq[j][2], bq[j][3]);
                }
            // lo*hi
#pragma unroll
            for (int t = 0; t < 4; t++)
#pragma unroll
                for (int j = 0; j < 4; j++) {
                    MMA(acc[t][2 * j],     al[t], bq[j][0], bq[j][1]);
                    MMA(acc[t][2 * j + 1], al[t], bq[j][2], bq[j][3]);
                }
            // hi*lo
#pragma unroll
            for (int j = 0; j < 4; j++) LDSM4(bq[j], baddr[j] + ks * 32 + 128);
#pragma unroll
            for (int t = 0; t < 4; t++)
#pragma unroll
                for (int j = 0; j < 4; j++) {
                    MMA(acc[t][2 * j],     ah[t], bq[j][0], bq[j][1]);
                    MMA(acc[t][2 * j + 1], ah[t], bq[j][2], bq[j][3]);
                }
        }
        __syncthreads();
    }

    // ---- epilogue: regs -> smem transpose [oc][m] -> coalesced gmem --------
#pragma unroll
    for (int t = 0; t < 4; t++) {
        int r0 = warp_m * 64 + t * 16 + (lid >> 2);
#pragma unroll
        for (int nt = 0; nt < 8; nt++) {
            int c = warp_n * 64 + nt * 8 + 2 * (lid & 3);
            sEp[c * 258 + r0]           = acc[t][nt][0];
            sEp[(c + 1) * 258 + r0]     = acc[t][nt][1];
            sEp[c * 258 + r0 + 8]       = acc[t][nt][2];
            sEp[(c + 1) * 258 + r0 + 8] = acc[t][nt][3];
        }
    }
    __syncthreads();

    if (zmode) {
        int slot = tid >> 6, p = tid & 63;
        bool valid = p < 36;
        size_t base = ((size_t)(img0 + slot) * COUT + ocb) * 36 + p;
        for (int k = 0; k < 128; k++) {
            float v = sEp[k * 258 + tid] + g_bias[path][ocb + k];
            if (valid) outp[base + (size_t)k * 36] = v;
        }
    } else {
        int y = row0 + (tid >> 5), x = tid & 31;
        bool valid = (y < 30) && (x < 30);
        size_t base = ((size_t)img0 * COUT + ocb) * 900 + y * 30 + x;
        for (int k = 0; k < 128; k++) {
            float v = sEp[k * 258 + tid] + g_bias[path][ocb + k];
            if (valid) outp[base + (size_t)k * 900] = v;
        }
    }
}

// ============================ depthwise xcorr ================================
__global__ __launch_bounds__(640)
void xcorr_kernel(float* __restrict__ out) {
    __shared__ float s_x[900];
    __shared__ float s_z[36];
    const int branch = blockIdx.y;
    const int bc = blockIdx.x;
    const int tid = threadIdx.x;
    if (tid < 36) s_z[tid] = g_zf[branch][(size_t)bc * 36 + tid];
    for (int i = tid; i < 900; i += 640) s_x[i] = g_xf[branch][(size_t)bc * 900 + i];
    __syncthreads();
    if (tid < 625) {
        int oy = tid / 25, ox = tid % 25;
        float s = 0.f;
#pragma unroll
        for (int u = 0; u < 6; u++)
#pragma unroll
            for (int v = 0; v < 6; v++)
                s = fmaf(s_z[u * 6 + v], s_x[(oy + u) * 30 + ox + v], s);
        out[(size_t)branch * OSZ + (size_t)bc * 625 + tid] = s;
    }
}

// ============================ launch =========================================
extern "C" void kernel_launch(void* const* d_in, const int* in_sizes, int n_in,
                              void* d_out, int out_size) {
    const float* z = (const float*)d_in[0];
    const float* x = (const float*)d_in[1];

    PrepArgs pa;
    for (int p = 0; p < 4; p++) {
        pa.w[p] = (const float*)d_in[2 + p * 5 + 0];
        pa.g[p] = (const float*)d_in[2 + p * 5 + 1];
        pa.b[p] = (const float*)d_in[2 + p * 5 + 2];
        pa.m[p] = (const float*)d_in[2 + p * 5 + 3];
        pa.v[p] = (const float*)d_in[2 + p * 5 + 4];
    }

    cudaFuncSetAttribute(conv_mma_kernel,
                         cudaFuncAttributeMaxDynamicSharedMemorySize, CONV_SMEM);

    prep_kernel<<<1152, 256>>>(pa);
    conv_mma_kernel<<<544, 256, CONV_SMEM>>>(z, x);
    xcorr_kernel<<<dim3(NB * COUT, 2), 640>>>((float*)d_out);
}

// round 5
// speedup vs baseline: 4.7942x; 1.4612x over previous
#include <cuda_runtime.h>
#include <cuda_bf16.h>
#include <cstdint>

#define CIN 256
#define COUT 256
#define NB 32
#define ZSZ (NB * COUT * 36)
#define XSZ (NB * COUT * 900)
#define OSZ (NB * COUT * 625)
#define WB_PER_PATH (9 * 256 * 512)

__device__ __nv_bfloat16 g_wb[4][WB_PER_PATH];  // [path][tap][oc][hi 256 | lo 256]
__device__ float g_bias[4][COUT];
__device__ float g_zf[2][ZSZ];
__device__ float g_xf[2][XSZ];

struct PrepArgs {
    const float* w[4];
    const float* g[4];
    const float* b[4];
    const float* m[4];
    const float* v[4];
};

// ============================ helpers ========================================
__device__ __forceinline__ uint32_t smem_u32(const void* p) {
    uint32_t a;
    asm("{ .reg .u64 t; cvta.to.shared.u64 t, %1; cvt.u32.u64 %0, t; }"
        : "=r"(a) : "l"(p));
    return a;
}
__device__ __forceinline__ void cp16(uint32_t dst, const void* src) {
    asm volatile("cp.async.cg.shared.global [%0], [%1], 16;" :: "r"(dst), "l"(src));
}
__device__ __forceinline__ void cp_commit() {
    asm volatile("cp.async.commit_group;" ::: "memory");
}
template <int N>
__device__ __forceinline__ void cp_wait() {
    asm volatile("cp.async.wait_group %0;" :: "n"(N) : "memory");
}

#define LDSM4(r, addr)                                                         \
    asm volatile("ldmatrix.sync.aligned.m8n8.x4.shared.b16 {%0,%1,%2,%3},[%4];"\
        : "=r"((r)[0]), "=r"((r)[1]), "=r"((r)[2]), "=r"((r)[3]) : "r"(addr))

#define MMA(d, a, b0, b1)                                                      \
    asm volatile("mma.sync.aligned.m16n8k16.row.col.f32.bf16.bf16.f32 "        \
        "{%0,%1,%2,%3}, {%4,%5,%6,%7}, {%8,%9}, {%0,%1,%2,%3};"                \
        : "+f"((d)[0]), "+f"((d)[1]), "+f"((d)[2]), "+f"((d)[3])               \
        : "r"((a)[0]), "r"((a)[1]), "r"((a)[2]), "r"((a)[3]),                  \
          "r"(b0), "r"(b1))

__device__ __forceinline__ uint32_t split_pack(float v0, float v1, uint32_t& lo) {
    __nv_bfloat16 h0 = __float2bfloat16(v0);
    __nv_bfloat16 h1 = __float2bfloat16(v1);
    __nv_bfloat16 l0 = __float2bfloat16(v0 - __bfloat162float(h0));
    __nv_bfloat16 l1 = __float2bfloat16(v1 - __bfloat162float(h1));
    lo = (uint32_t)__bfloat16_as_ushort(l0) | ((uint32_t)__bfloat16_as_ushort(l1) << 16);
    return (uint32_t)__bfloat16_as_ushort(h0) | ((uint32_t)__bfloat16_as_ushort(h1) << 16);
}

// ============================ prep ===========================================
__global__ void prep_kernel(PrepArgs a) {
    const int TOTAL = 4 * 9 * 256 * 256;
    for (int i = blockIdx.x * blockDim.x + threadIdx.x; i < TOTAL;
         i += gridDim.x * blockDim.x) {
        int path = i / (9 * 256 * 256);
        int q    = i % (9 * 256 * 256);
        int tap  = q >> 16;
        int oc   = (q >> 8) & 255;
        int cin  = q & 255;
        float inv = a.g[path][oc] * rsqrtf(a.v[path][oc] + 1e-5f);
        float ws  = a.w[path][oc * 2304 + cin * 9 + tap] * inv;
        __nv_bfloat16 hi = __float2bfloat16(ws);
        __nv_bfloat16 lo = __float2bfloat16(ws - __bfloat162float(hi));
        g_wb[path][(tap * 256 + oc) * 512 + cin]       = hi;
        g_wb[path][(tap * 256 + oc) * 512 + 256 + cin] = lo;
        if (i < 4 * 256) {
            int p2 = i >> 8, oc2 = i & 255;
            float inv2 = a.g[p2][oc2] * rsqrtf(a.v[p2][oc2] + 1e-5f);
            g_bias[p2][oc2] = a.b[p2][oc2] - a.m[p2][oc2] * inv2;
        }
    }
}

// ============================ conv (HMMA implicit GEMM) ======================
// Block: M=128 px x N=128 oc, K = 256 cin x 9 taps (chunked 32 cins), 128 thr.
// 4 warps = 2(M) x 2(N); warp tile 64x64; 2 CTAs/SM for overlap.
// blocks 0..959: x-mode, dense global out-row packing (4 rows/block)
// blocks 960..995: z-mode, dense pixel packing (128 px/block, 1152=9*128)
#define BSTRIDE 144u                 // B row bytes: 32 hi (64) + 32 lo (64) + 16 pad
#define BBUF    (128u * BSTRIDE)     // 18432
#define RAW_OFF (2u * BBUF)          // 36864
#define SSTRIDE 80u                  // raw slot bytes: 32 cins (64B) + 16 pad
#define NSLOTS  320u
#define SLABB   (NSLOTS * SSTRIDE)   // 25600 (hi slab; lo at +SLABB)
#define CONV_SMEM (RAW_OFF + 2u * SLABB)   // 88064

__device__ __forceinline__ void copy_B(uint32_t sBu, const __nv_bfloat16* wb,
                                       int ocb, int g, int tid) {
    int chunk = 0, t = g;
    while (t >= 9) { t -= 9; chunk++; }
    const int buf = g & 1, c0 = chunk * 32;
    const __nv_bfloat16* base = wb + (size_t)(t * 256 + ocb) * 512;
#pragma unroll
    for (int k = 0; k < 8; k++) {
        int id = tid + k * 128;           // 1024 cp16 total
        int n = id >> 3, q = id & 7, comp = q >> 2, kq = q & 3;
        uint32_t dst = sBu + buf * BBUF + n * BSTRIDE + comp * 64 + kq * 16;
        cp16(dst, base + (size_t)n * 512 + comp * 256 + c0 + kq * 8);
    }
    cp_commit();
}

__global__ __launch_bounds__(128, 2)
void conv_mma_kernel(const float* __restrict__ zin,
                     const float* __restrict__ xin) {
    extern __shared__ __align__(16) char smem[];
    const int tid = threadIdx.x, lid = tid & 31, wid = tid >> 5;
    const int warp_m = wid >> 1, warp_n = wid & 1;
    const uint32_t sBu  = smem_u32(smem);
    const uint32_t rawu = sBu + RAW_OFF;

    const int bid = blockIdx.x;
    const bool zmode = (bid >= 960);
    int branch, ocb;
    int R0 = 0, img0 = 0, y0 = 0, s = 4;   // x-mode
    int P0 = 0, img_base = 0;              // z-mode
    if (zmode) {
        int zb = bid - 960;                // 0..35
        int bo = zb / 9;
        branch = bo >> 1; ocb = (bo & 1) * 128;
        P0 = (zb - bo * 9) * 128;
        img_base = P0 / 36;
    } else {
        int bo = bid / 240;
        branch = bo >> 1; ocb = (bo & 1) * 128;
        R0 = (bid - bo * 240) * 4;
        img0 = R0 / 30; y0 = R0 - img0 * 30;
        s = 30 - y0; if (s > 4) s = 4;
    }
    const int path = zmode ? 2 * branch : 1 + 2 * branch;
    const __nv_bfloat16* wb = g_wb[path];
    const float* in = zmode ? zin : xin;

    float acc[2][8][4];
#pragma unroll
    for (int t = 0; t < 2; t++)
#pragma unroll
        for (int j = 0; j < 8; j++)
#pragma unroll
            for (int e = 0; e < 4; e++) acc[t][j][e] = 0.f;
    // warp tile is 64x64 -> 4 m16 tiles; use acc2 for upper two
    float acc2[2][8][4];
#pragma unroll
    for (int t = 0; t < 2; t++)
#pragma unroll
        for (int j = 0; j < 8; j++)
#pragma unroll
            for (int e = 0; e < 4; e++) acc2[t][j][e] = 0.f;

    copy_B(sBu, wb, ocb, 0, tid);

    int chunk = 0, tap = 0;
#pragma unroll 1
    for (int g = 0; g < 72; g++) {
        const int buf = g & 1;
        __syncthreads();   // all warps done consuming raw/B from g-1
        if (tap == 0) {
            const int c0 = chunk * 32;
            if (zmode) {
                // 5 images x 64 px x 16 cin-pairs = 5120 ids, 40/thread
#pragma unroll 4
                for (int k = 0; k < 40; k++) {
                    int id = tid + k * 128;
                    int pos = id & 63;
                    int rest = id >> 6;
                    int ir = rest % 5, cp = rest / 5;
                    int img = img_base + ir;
                    int c = c0 + cp * 2;
                    float v0 = 0.f, v1 = 0.f;
                    if (img < 32) {
                        const float* src = in + (((size_t)img * 256 + c) << 6) + pos;
                        v0 = src[0];
                        v1 = src[64];
                    }
                    uint32_t lo, hi = split_pack(v0, v1, lo);
                    uint32_t ad = rawu + (ir * 64 + pos) * SSTRIDE + cp * 4;
                    *(uint32_t*)(smem + (ad - sBu))        = hi;
                    *(uint32_t*)(smem + (ad - sBu) + SLABB) = lo;
                }
            } else {
                // 8 rows x 32 cols x 16 cin-pairs = 4096 ids, 32/thread
#pragma unroll 4
                for (int k = 0; k < 32; k++) {
                    int id = tid + k * 128;
                    int col = id & 31;
                    int r = (id >> 5) & 7;
                    int cp = id >> 8;
                    int img, yin;
                    if (s < 4) {
                        if (r < s + 2) { img = img0;     yin = y0 + r; }
                        else           { img = img0 + 1; yin = r - s - 2; }
                    } else {
                        img = img0; yin = y0 + r; if (yin > 31) yin = 31;
                    }
                    int c = c0 + cp * 2;
                    const float* src = in + (((size_t)img * 256 + c) * 32 + yin) * 32 + col;
                    float v0 = src[0];
                    float v1 = src[1024];
                    uint32_t lo, hi = split_pack(v0, v1, lo);
                    uint32_t off = RAW_OFF + (r * 32 + col) * SSTRIDE + cp * 4;
                    *(uint32_t*)(smem + off)         = hi;
                    *(uint32_t*)(smem + off + SLABB) = lo;
                }
            }
        }
        if (g + 1 < 72) { copy_B(sBu, wb, ocb, g + 1, tid); cp_wait<1>(); }
        else            { cp_wait<0>(); }
        __syncthreads();

        const int dy = tap / 3, dx = tap - dy * 3;
        uint32_t aaddr[4], baddr[4];
#pragma unroll
        for (int t = 0; t < 4; t++) {
            int m = warp_m * 64 + t * 16 + (lid & 7) + ((lid >> 3) & 1) * 8;
            int slot;
            if (zmode) {
                int p = P0 + m;
                int pim = p / 36;
                int q = p - pim * 36;
                int qy = q / 6;
                slot = (pim - img_base) * 64 + (qy + dy) * 8 + (q - qy * 6) + dx;
            } else {
                int i = m >> 5, x = m & 31;
                int sr = i + dy + ((i >= s) ? 2 : 0);
                slot = sr * 32 + x + dx;
            }
            aaddr[t] = rawu + slot * SSTRIDE + ((lid >> 4) << 4);
        }
#pragma unroll
        for (int j = 0; j < 4; j++) {
            int n = warp_n * 64 + j * 16 + (lid & 7) + (lid >> 4) * 8;
            baddr[j] = sBu + buf * BBUF + n * BSTRIDE + (((lid >> 3) & 1) << 4);
        }

#pragma unroll
        for (int ks = 0; ks < 2; ks++) {
            uint32_t ah[4][4], al[4][4], bq[4][4];
#pragma unroll
            for (int t = 0; t < 4; t++) LDSM4(ah[t], aaddr[t] + ks * 32);
#pragma unroll
            for (int t = 0; t < 4; t++) LDSM4(al[t], aaddr[t] + ks * 32 + SLABB);
#pragma unroll
            for (int j = 0; j < 4; j++) LDSM4(bq[j], baddr[j] + ks * 32);
            // hi*hi and lo*hi
#pragma unroll
            for (int t = 0; t < 4; t++) {
                float (*ac)[4] = (t < 2) ? acc[t] : acc2[t - 2];
#pragma unroll
                for (int j = 0; j < 4; j++) {
                    MMA(ac[2 * j],     ah[t], bq[j][0], bq[j][1]);
                    MMA(ac[2 * j + 1], ah[t], bq[j][2], bq[j][3]);
                }
            }
#pragma unroll
            for (int t = 0; t < 4; t++) {
                float (*ac)[4] = (t < 2) ? acc[t] : acc2[t - 2];
#pragma unroll
                for (int j = 0; j < 4; j++) {
                    MMA(ac[2 * j],     al[t], bq[j][0], bq[j][1]);
                    MMA(ac[2 * j + 1], al[t], bq[j][2], bq[j][3]);
                }
            }
            // hi*lo
#pragma unroll
            for (int j = 0; j < 4; j++) LDSM4(bq[j], baddr[j] + 64 + ks * 32);
#pragma unroll
            for (int t = 0; t < 4; t++) {
                float (*ac)[4] = (t < 2) ? acc[t] : acc2[t - 2];
#pragma unroll
                for (int j = 0; j < 4; j++) {
                    MMA(ac[2 * j],     ah[t], bq[j][0], bq[j][1]);
                    MMA(ac[2 * j + 1], ah[t], bq[j][2], bq[j][3]);
                }
            }
        }
        if (++tap == 9) { tap = 0; chunk++; }
    }
    __syncthreads();

    // ---- epilogue: regs -> smem transpose [oc][m] -> coalesced out ---------
    float* sEp = (float*)smem;                    // 128 x 132 floats
    float* sBias = (float*)(smem + 128 * 132 * 4);
    if (tid < 128) sBias[tid] = g_bias[path][ocb + tid];
#pragma unroll
    for (int t = 0; t < 4; t++) {
        float (*ac)[4] = (t < 2) ? acc[t] : acc2[t - 2];
        int r0 = warp_m * 64 + t * 16 + (lid >> 2);
#pragma unroll
        for (int nt = 0; nt < 8; nt++) {
            int c = warp_n * 64 + nt * 8 + 2 * (lid & 3);
            sEp[c * 132 + r0]           = ac[nt][0];
            sEp[(c + 1) * 132 + r0]     = ac[nt][1];
            sEp[c * 132 + r0 + 8]       = ac[nt][2];
            sEp[(c + 1) * 132 + r0 + 8] = ac[nt][3];
        }
    }
    __syncthreads();

    if (zmode) {
        int p = P0 + tid;
        int img = p / 36;
        int q = p - img * 36;
        float* op = g_zf[branch] + ((size_t)img * COUT + ocb) * 36 + q;
#pragma unroll 8
        for (int k = 0; k < 128; k++)
            op[(size_t)k * 36] = sEp[k * 132 + tid] + sBias[k];
    } else {
        int R = R0 + (tid >> 5);
        int x = tid & 31;
        int img = R / 30, y = R - img * 30;
        if (x < 30) {
            float* op = g_xf[branch] + ((size_t)img * COUT + ocb) * 900 + y * 30 + x;
#pragma unroll 8
            for (int k = 0; k < 128; k++)
                op[(size_t)k * 900] = sEp[k * 132 + tid] + sBias[k];
        }
    }
}

// ============================ depthwise xcorr ================================
__global__ __launch_bounds__(640)
void xcorr_kernel(float* __restrict__ out) {
    __shared__ float s_x[900];
    __shared__ float s_z[36];
    const int branch = blockIdx.y;
    const int bc = blockIdx.x;
    const int tid = threadIdx.x;
    if (tid < 36) s_z[tid] = g_zf[branch][(size_t)bc * 36 + tid];
    for (int i = tid; i < 900; i += 640) s_x[i] = g_xf[branch][(size_t)bc * 900 + i];
    __syncthreads();
    if (tid < 625) {
        int oy = tid / 25, ox = tid % 25;
        float s = 0.f;
#pragma unroll
        for (int u = 0; u < 6; u++)
#pragma unroll
            for (int v = 0; v < 6; v++)
                s = fmaf(s_z[u * 6 + v], s_x[(oy + u) * 30 + ox + v], s);
        out[(size_t)branch * OSZ + (size_t)bc * 625 + tid] = s;
    }
}

// ============================ launch =========================================
extern "C" void kernel_launch(void* const* d_in, const int* in_sizes, int n_in,
                              void* d_out, int out_size) {
    const float* z = (const float*)d_in[0];
    const float* x = (const float*)d_in[1];

    PrepArgs pa;
    for (int p = 0; p < 4; p++) {
        pa.w[p] = (const float*)d_in[2 + p * 5 + 0];
        pa.g[p] = (const float*)d_in[2 + p * 5 + 1];
        pa.b[p] = (const float*)d_in[2 + p * 5 + 2];
        pa.m[p] = (const float*)d_in[2 + p * 5 + 3];
        pa.v[p] = (const float*)d_in[2 + p * 5 + 4];
    }

    cudaFuncSetAttribute(conv_mma_kernel,
                         cudaFuncAttributeMaxDynamicSharedMemorySize, CONV_SMEM);
    cudaFuncSetAttribute(conv_mma_kernel,
                         cudaFuncAttributePreferredSharedMemoryCarveout, 100);

    prep_kernel<<<1152, 256>>>(pa);
    conv_mma_kernel<<<996, 128, CONV_SMEM>>>(z, x);
    xcorr_kernel<<<dim3(NB * COUT, 2), 640>>>((float*)d_out);
}